// round 13
// baseline (speedup 1.0000x reference)
#include <cuda_runtime.h>

// PraxisCompressiveMemory (Infini-attention delta-rule memory), single segment.
// Shapes: B=4, H=32, S=2048, D=128, all fp32.
// out        = sigmoid(betas) * (sq@M)/(sq@z) + (1-sigmoid(betas)) * att
// new_states = M + sk^T @ (v - (sk@M)/(sk@z))
// new_z      = z + colsum(sk)
// where sq = elu(q)+1, sk = elu(k)+1.
//
// One CTA per (b,h). 512 threads (4 warps/SMSP for latency hiding).
// Rank-update accumulator in registers (f32x2 packed, 4x8 tile/thread),
// M / sigma tiles / value-delta staged in dynamic smem.
// All heavy loops use packed fma.rn.f32x2 (2x fp32 rate on sm_103a).

#define Bc 4
#define Hc 32
#define Sc 2048
#define Dc 128

static constexpr int RCH = 64;           // s-rows per chunk
static constexpr int NCH = Sc / RCH;     // 32 chunks
static constexpr int NTHREADS = 512;

static constexpr long long OUT_ELEMS = (long long)Bc * Hc * Sc * Dc;   // 33554432
static constexpr long long NS_OFF    = OUT_ELEMS;                       // new_states base
static constexpr long long NZ_OFF    = NS_OFF + (long long)Bc * Hc * Dc * Dc; // new_z base

// smem layout (float offsets)
static constexpr int SM_M  = 0;              // M       [128][128]
static constexpr int SM_A  = 16384;          // sigma   [128][128] (0-63 q, 64-127 k)
static constexpr int SM_VD = 32768;          // v-delta [64][128]
static constexpr int SM_Z  = 40960;          // init_z  [128]
static constexpr int SM_G  = 41088;          // gate    [128]
static constexpr int SM_DI = 41216;          // 1/denom [128]
static constexpr int SM_TOT = 41344;         // floats -> 165376 bytes

__device__ __forceinline__ unsigned long long dup2(float x) {
    unsigned long long r;
    unsigned int u = __float_as_uint(x);
    asm("mov.b64 %0, {%1, %1};" : "=l"(r) : "r"(u));
    return r;
}
__device__ __forceinline__ void ffma2(unsigned long long& d,
                                      unsigned long long a,
                                      unsigned long long b) {
    asm("fma.rn.f32x2 %0, %1, %2, %0;" : "+l"(d) : "l"(a), "l"(b));
}
__device__ __forceinline__ void unpack2(unsigned long long v, float& lo, float& hi) {
    unsigned int a, b;
    asm("mov.b64 {%0, %1}, %2;" : "=r"(a), "=r"(b) : "l"(v));
    lo = __uint_as_float(a);
    hi = __uint_as_float(b);
}
__device__ __forceinline__ float sigmaf(float x) {
    // elu(x)+1  ==  x+1 (x>0) else exp(x)
    return x > 0.0f ? x + 1.0f : __expf(x);
}
__device__ __forceinline__ float4 sigma4(float4 t) {
    t.x = sigmaf(t.x); t.y = sigmaf(t.y); t.z = sigmaf(t.z); t.w = sigmaf(t.w);
    return t;
}
__device__ __forceinline__ float wredsum(float v) {
    v += __shfl_xor_sync(0xffffffffu, v, 16);
    v += __shfl_xor_sync(0xffffffffu, v, 8);
    v += __shfl_xor_sync(0xffffffffu, v, 4);
    v += __shfl_xor_sync(0xffffffffu, v, 2);
    v += __shfl_xor_sync(0xffffffffu, v, 1);
    return v;
}

__global__ void __launch_bounds__(NTHREADS, 1)
pcm_kernel(const float* __restrict__ q, const float* __restrict__ k,
           const float* __restrict__ v, const float* __restrict__ att,
           const float* __restrict__ betas, const float* __restrict__ mem0,
           const float* __restrict__ z0, float* __restrict__ out)
{
    extern __shared__ float sm[];
    float* Msm  = sm + SM_M;
    float* Asm  = sm + SM_A;
    float* VDsm = sm + SM_VD;
    float* zsm  = sm + SM_Z;
    float* gsm  = sm + SM_G;
    float* dinv = sm + SM_DI;

    const int tid = threadIdx.x;
    const int bh  = blockIdx.x;           // 0..127
    const int h   = bh & (Hc - 1);
    const long long sbase = (long long)bh * Sc * Dc;

    // ---- block init: load M, init_z, gate = sigmoid(betas) ----
    {
        const float4* src = (const float4*)(mem0 + (long long)h * Dc * Dc);
        float4* dst = (float4*)Msm;
        #pragma unroll
        for (int j = 0; j < 8; j++) dst[tid + NTHREADS * j] = src[tid + NTHREADS * j];
    }
    if (tid < Dc) {
        zsm[tid] = z0[h * Dc + tid];
        float bt = betas[h * Dc + tid];
        gsm[tid] = 1.0f / (1.0f + __expf(-bt));
    }
    __syncthreads();

    const int lane = tid & 31;
    const int warp = tid >> 5;            // 0..15
    const int rg   = tid >> 4;            // 0..31 : rows rg*4..rg*4+3
    const int cg   = tid & 15;            // 0..15 : cols cg*8..cg*8+7
    const int cols = cg * 8;

    // per-lane init_z float4 slice for the fused denominator reduction
    const float4 z4 = *(const float4*)(zsm + lane * 4);

    // persistent rank-update accumulator: d-rows rg*4.., d'-cols cg*8.. (f32x2 pairs)
    unsigned long long racc[4][4];
    #pragma unroll
    for (int i = 0; i < 4; i++) {
        #pragma unroll
        for (int j = 0; j < 4; j++) racc[i][j] = 0ULL;
    }
    float zacc = 0.0f;

    for (int ch = 0; ch < NCH; ch++) {
        const int s0 = ch * RCH;

        // ---- phase A (fused): sigma(q)->Asm[0..63], sigma(k)->Asm[64..127],
        //      plus 1/(sigma_row . init_z) -> dinv, all warp-local ----
        {
            const float4* qsrc = (const float4*)(q + sbase + (long long)s0 * Dc);
            const float4* ksrc = (const float4*)(k + sbase + (long long)s0 * Dc);
            float4* aq = (float4*)Asm;
            float4* ak = (float4*)(Asm + 64 * Dc);
            #pragma unroll
            for (int j = 0; j < 4; j++) {
                int row = warp * 4 + j;           // 0..63 (one full row per warp)
                int fid = row * 32 + lane;
                float4 sq = sigma4(qsrc[fid]);
                aq[fid] = sq;
                float vq = sq.x * z4.x + sq.y * z4.y + sq.z * z4.z + sq.w * z4.w;
                vq = wredsum(vq);
                if (lane == 0) dinv[row] = 1.0f / vq;

                float4 sk = sigma4(ksrc[fid]);
                ak[fid] = sk;
                float vk = sk.x * z4.x + sk.y * z4.y + sk.z * z4.z + sk.w * z4.w;
                vk = wredsum(vk);
                if (lane == 0) dinv[64 + row] = 1.0f / vk;
            }
        }
        __syncthreads();

        // ---- GEMM: C[128][128] = Asm @ Msm, 4x8 thread tiles, f32x2 packed ----
        unsigned long long cacc[4][4];
        #pragma unroll
        for (int i = 0; i < 4; i++) {
            #pragma unroll
            for (int j = 0; j < 4; j++) cacc[i][j] = 0ULL;
        }
        {
            const float* arow = Asm + rg * 4 * Dc;
            #pragma unroll 2
            for (int k4 = 0; k4 < Dc / 4; k4++) {
                float4 a4[4];
                #pragma unroll
                for (int i = 0; i < 4; i++)
                    a4[i] = *(const float4*)(arow + i * Dc + k4 * 4);
                #pragma unroll
                for (int kk = 0; kk < 4; kk++) {
                    const ulonglong2* mp =
                        (const ulonglong2*)(Msm + (k4 * 4 + kk) * Dc + cols);
                    ulonglong2 b0 = mp[0];
                    ulonglong2 b1 = mp[1];
                    #pragma unroll
                    for (int i = 0; i < 4; i++) {
                        float av = (kk == 0) ? a4[i].x : (kk == 1) ? a4[i].y
                                 : (kk == 2) ? a4[i].z : a4[i].w;
                        unsigned long long a2 = dup2(av);
                        ffma2(cacc[i][0], a2, b0.x);
                        ffma2(cacc[i][1], a2, b0.y);
                        ffma2(cacc[i][2], a2, b1.x);
                        ffma2(cacc[i][3], a2, b1.y);
                    }
                }
            }
        }

        // ---- epilogue: rows<64 -> gated output; rows>=64 -> value-delta ----
        if (rg < 16) {      // q rows (warps 0-7, uniform per warp)
            float4 g0 = *(const float4*)(gsm + cols);
            float4 g1 = *(const float4*)(gsm + cols + 4);
            #pragma unroll
            for (int i = 0; i < 4; i++) {
                int row = rg * 4 + i;
                float inv = dinv[row];
                float c[8];
                unpack2(cacc[i][0], c[0], c[1]);
                unpack2(cacc[i][1], c[2], c[3]);
                unpack2(cacc[i][2], c[4], c[5]);
                unpack2(cacc[i][3], c[6], c[7]);
                const long long rowoff = sbase + (long long)(s0 + row) * Dc + cols;
                const float4* ap = (const float4*)(att + rowoff);
                float4 a0 = ap[0], a1 = ap[1];
                float4 o0, o1;
                o0.x = g0.x * (c[0] * inv) + (1.0f - g0.x) * a0.x;
                o0.y = g0.y * (c[1] * inv) + (1.0f - g0.y) * a0.y;
                o0.z = g0.z * (c[2] * inv) + (1.0f - g0.z) * a0.z;
                o0.w = g0.w * (c[3] * inv) + (1.0f - g0.w) * a0.w;
                o1.x = g1.x * (c[4] * inv) + (1.0f - g1.x) * a1.x;
                o1.y = g1.y * (c[5] * inv) + (1.0f - g1.y) * a1.y;
                o1.z = g1.z * (c[6] * inv) + (1.0f - g1.z) * a1.z;
                o1.w = g1.w * (c[7] * inv) + (1.0f - g1.w) * a1.w;
                float4* op = (float4*)(out + rowoff);
                op[0] = o0; op[1] = o1;
            }
        } else {            // k rows (warps 8-15): vd = v - retrieved -> VDsm
            #pragma unroll
            for (int i = 0; i < 4; i++) {
                int row = rg * 4 + i;          // 64..127
                int r   = row - 64;
                float inv = dinv[row];
                float c[8];
                unpack2(cacc[i][0], c[0], c[1]);
                unpack2(cacc[i][1], c[2], c[3]);
                unpack2(cacc[i][2], c[4], c[5]);
                unpack2(cacc[i][3], c[6], c[7]);
                const float4* vp =
                    (const float4*)(v + sbase + (long long)(s0 + r) * Dc + cols);
                float4 v0 = vp[0], v1 = vp[1];
                float4 w0, w1;
                w0.x = v0.x - c[0] * inv;  w0.y = v0.y - c[1] * inv;
                w0.z = v0.z - c[2] * inv;  w0.w = v0.w - c[3] * inv;
                w1.x = v1.x - c[4] * inv;  w1.y = v1.y - c[5] * inv;
                w1.z = v1.z - c[6] * inv;  w1.w = v1.w - c[7] * inv;
                float4* wp = (float4*)(VDsm + r * Dc + cols);
                wp[0] = w0; wp[1] = w1;
            }
        }
        __syncthreads();

        // ---- rank-64 update: racc[d][d'] += sk[r][d] * vd[r][d'] ----
        {
            const int drow = rg * 4;
            #pragma unroll 2
            for (int r = 0; r < RCH; r++) {
                float4 sA = *(const float4*)(Asm + (64 + r) * Dc + drow);
                const ulonglong2* vp = (const ulonglong2*)(VDsm + r * Dc + cols);
                ulonglong2 b0 = vp[0];
                ulonglong2 b1 = vp[1];
                #pragma unroll
                for (int i = 0; i < 4; i++) {
                    float sv = (i == 0) ? sA.x : (i == 1) ? sA.y
                             : (i == 2) ? sA.z : sA.w;
                    unsigned long long a2 = dup2(sv);
                    ffma2(racc[i][0], a2, b0.x);
                    ffma2(racc[i][1], a2, b0.y);
                    ffma2(racc[i][2], a2, b1.x);
                    ffma2(racc[i][3], a2, b1.y);
                }
            }
            if (tid < Dc) {
                float zs = 0.0f;
                #pragma unroll 8
                for (int r = 0; r < RCH; r++) zs += Asm[(64 + r) * Dc + tid];
                zacc += zs;
            }
        }
        __syncthreads();   // protect Asm/VDsm before next chunk
    }

    // ---- final: new_states = M + racc, new_z = z + zacc ----
    {
        float* ns = out + NS_OFF + (long long)bh * Dc * Dc;
        #pragma unroll
        for (int i = 0; i < 4; i++) {
            int drow = rg * 4 + i;
            float c[8];
            unpack2(racc[i][0], c[0], c[1]);
            unpack2(racc[i][1], c[2], c[3]);
            unpack2(racc[i][2], c[4], c[5]);
            unpack2(racc[i][3], c[6], c[7]);
            const float* mrow = Msm + drow * Dc + cols;
            float4 r0, r1;
            r0.x = c[0] + mrow[0];  r0.y = c[1] + mrow[1];
            r0.z = c[2] + mrow[2];  r0.w = c[3] + mrow[3];
            r1.x = c[4] + mrow[4];  r1.y = c[5] + mrow[5];
            r1.z = c[6] + mrow[6];  r1.w = c[7] + mrow[7];
            float4* np = (float4*)(ns + drow * Dc + cols);
            np[0] = r0; np[1] = r1;
        }
        if (tid < Dc) {
            out[NZ_OFF + (long long)bh * Dc + tid] = zsm[tid] + zacc;
        }
    }
}

extern "C" void kernel_launch(void* const* d_in, const int* in_sizes, int n_in,
                              void* d_out, int out_size) {
    (void)in_sizes; (void)n_in; (void)out_size;
    const float* q    = (const float*)d_in[0];
    const float* k    = (const float*)d_in[1];
    const float* v    = (const float*)d_in[2];
    const float* att  = (const float*)d_in[3];
    const float* bet  = (const float*)d_in[4];
    const float* mem0 = (const float*)d_in[5];
    const float* z0   = (const float*)d_in[6];
    float* out = (float*)d_out;

    const int smem_bytes = SM_TOT * (int)sizeof(float);   // 165376
    cudaFuncSetAttribute(pcm_kernel,
                         cudaFuncAttributeMaxDynamicSharedMemorySize, smem_bytes);
    pcm_kernel<<<Bc * Hc, NTHREADS, smem_bytes>>>(q, k, v, att, bet, mem0, z0, out);
}

// round 14
// speedup vs baseline: 1.5418x; 1.5418x over previous
#include <cuda_runtime.h>
#include <cstdint>

// PraxisCompressiveMemory (Infini-attention delta-rule memory), single segment.
// Shapes: B=4, H=32, S=2048, D=128, all fp32.
// out        = sigmoid(betas) * (sq@M)/(sq@z) + (1-sigmoid(betas)) * att
// new_states = M + sk^T @ (v - (sk@M)/(sk@z))
// new_z      = z + colsum(sk)
// where sq = elu(q)+1, sk = elu(k)+1.
//
// One CTA per (b,h), 256 threads, 8x8 register tiles (proven no-spill shape).
// cp.async pipeline stages next chunk's raw q/k into smem so phase A never
// waits on DRAM. Heavy loops use packed fma.rn.f32x2.

#define Bc 4
#define Hc 32
#define Sc 2048
#define Dc 128

static constexpr int RCH = 64;           // s-rows per chunk
static constexpr int NCH = Sc / RCH;     // 32 chunks
static constexpr int NTHREADS = 256;

static constexpr long long OUT_ELEMS = (long long)Bc * Hc * Sc * Dc;
static constexpr long long NS_OFF    = OUT_ELEMS;
static constexpr long long NZ_OFF    = NS_OFF + (long long)Bc * Hc * Dc * Dc;

// smem layout (float offsets)
static constexpr int SM_M   = 0;             // M        [128][128]
static constexpr int SM_A   = 16384;         // sigma    [128][128] (0-63 q, 64-127 k)
static constexpr int SM_VD  = 32768;         // v-delta  [64][128]
static constexpr int SM_RAW = 40960;         // raw q[64][128] then k[64][128]
static constexpr int SM_Z   = 57344;         // init_z   [128]
static constexpr int SM_G   = 57472;         // gate     [128]
static constexpr int SM_DI  = 57600;         // 1/denom  [128]
static constexpr int SM_TOT = 57728;         // floats -> 230912 bytes

__device__ __forceinline__ unsigned long long dup2(float x) {
    unsigned long long r;
    unsigned int u = __float_as_uint(x);
    asm("mov.b64 %0, {%1, %1};" : "=l"(r) : "r"(u));
    return r;
}
__device__ __forceinline__ void ffma2(unsigned long long& d,
                                      unsigned long long a,
                                      unsigned long long b) {
    asm("fma.rn.f32x2 %0, %1, %2, %0;" : "+l"(d) : "l"(a), "l"(b));
}
__device__ __forceinline__ void unpack2(unsigned long long v, float& lo, float& hi) {
    unsigned int a, b;
    asm("mov.b64 {%0, %1}, %2;" : "=r"(a), "=r"(b) : "l"(v));
    lo = __uint_as_float(a);
    hi = __uint_as_float(b);
}
__device__ __forceinline__ float sigmaf(float x) {
    return x > 0.0f ? x + 1.0f : __expf(x);   // elu(x)+1
}
__device__ __forceinline__ float4 sigma4(float4 t) {
    t.x = sigmaf(t.x); t.y = sigmaf(t.y); t.z = sigmaf(t.z); t.w = sigmaf(t.w);
    return t;
}
__device__ __forceinline__ float wredsum(float v) {
    v += __shfl_xor_sync(0xffffffffu, v, 16);
    v += __shfl_xor_sync(0xffffffffu, v, 8);
    v += __shfl_xor_sync(0xffffffffu, v, 4);
    v += __shfl_xor_sync(0xffffffffu, v, 2);
    v += __shfl_xor_sync(0xffffffffu, v, 1);
    return v;
}
__device__ __forceinline__ void cp_async16(uint32_t dst, const void* src) {
    asm volatile("cp.async.cg.shared.global [%0], [%1], 16;"
                 :: "r"(dst), "l"(src));
}
__device__ __forceinline__ void cp_commit() {
    asm volatile("cp.async.commit_group;" ::: "memory");
}
__device__ __forceinline__ void cp_wait_all() {
    asm volatile("cp.async.wait_group 0;" ::: "memory");
}

__global__ void __launch_bounds__(NTHREADS, 1)
pcm_kernel(const float* __restrict__ q, const float* __restrict__ k,
           const float* __restrict__ v, const float* __restrict__ att,
           const float* __restrict__ betas, const float* __restrict__ mem0,
           const float* __restrict__ z0, float* __restrict__ out)
{
    extern __shared__ float sm[];
    float* Msm  = sm + SM_M;
    float* Asm  = sm + SM_A;
    float* VDsm = sm + SM_VD;
    float* zsm  = sm + SM_Z;
    float* gsm  = sm + SM_G;
    float* dinv = sm + SM_DI;

    const int tid = threadIdx.x;
    const int bh  = blockIdx.x;           // 0..127
    const int h   = bh & (Hc - 1);
    const long long sbase = (long long)bh * Sc * Dc;

    const uint32_t rawq_s = (uint32_t)__cvta_generic_to_shared(sm + SM_RAW);
    const uint32_t rawk_s = rawq_s + 64 * Dc * 4;

    // ---- block init: load M, init_z, gate = sigmoid(betas) ----
    {
        const float4* src = (const float4*)(mem0 + (long long)h * Dc * Dc);
        float4* dst = (float4*)Msm;
        #pragma unroll
        for (int j = 0; j < 16; j++) dst[tid + NTHREADS * j] = src[tid + NTHREADS * j];
    }
    if (tid < Dc) {
        zsm[tid] = z0[h * Dc + tid];
        float bt = betas[h * Dc + tid];
        gsm[tid] = 1.0f / (1.0f + __expf(-bt));
    }

    // prefetch chunk 0 raw q/k (16B per cp.async, 8 q + 8 k per thread)
    {
        const char* qs = (const char*)(q + sbase);
        const char* ks = (const char*)(k + sbase);
        #pragma unroll
        for (int j = 0; j < 8; j++) {
            int off = (tid + NTHREADS * j) * 16;
            cp_async16(rawq_s + off, qs + off);
            cp_async16(rawk_s + off, ks + off);
        }
        cp_commit();
    }
    __syncthreads();

    const int lane = tid & 31;
    const int warp = tid >> 5;            // 0..7
    const int rg   = tid >> 4;            // 0..15 : rows rg*8..rg*8+7
    const int cg   = tid & 15;            // 0..15 : cols cg*8..cg*8+7
    const int cols = cg * 8;

    // per-lane init_z float4 slice (cols lane*4..lane*4+3) for denom dot
    const float4 z4 = *(const float4*)(zsm + lane * 4);
    // per-thread gate for epilogue columns
    float gg[8], go[8];
    #pragma unroll
    for (int j = 0; j < 8; j++) { gg[j] = gsm[cols + j]; go[j] = 1.0f - gg[j]; }

    // persistent rank-update accumulator (f32x2 pairs)
    unsigned long long racc[8][4];
    #pragma unroll
    for (int i = 0; i < 8; i++) {
        #pragma unroll
        for (int j = 0; j < 4; j++) racc[i][j] = 0ULL;
    }
    float zacc = 0.0f;

    for (int ch = 0; ch < NCH; ch++) {
        const int s0 = ch * RCH;

        // ---- phase A: sigma + fused denominators from staged raw q/k ----
        cp_wait_all();
        __syncthreads();
        {
            const float4* rq = (const float4*)(sm + SM_RAW);
            const float4* rk = (const float4*)(sm + SM_RAW + 64 * Dc);
            float4* aq = (float4*)Asm;
            float4* ak = (float4*)(Asm + 64 * Dc);
            #pragma unroll
            for (int j = 0; j < 8; j++) {
                int row = warp * 8 + j;           // 0..63
                int fid = row * 32 + lane;
                float4 sq = sigma4(rq[fid]);
                aq[fid] = sq;
                float vq = sq.x * z4.x + sq.y * z4.y + sq.z * z4.z + sq.w * z4.w;
                vq = wredsum(vq);
                if (lane == 0) dinv[row] = 1.0f / vq;

                float4 sk = sigma4(rk[fid]);
                ak[fid] = sk;
                float vk = sk.x * z4.x + sk.y * z4.y + sk.z * z4.z + sk.w * z4.w;
                vk = wredsum(vk);
                if (lane == 0) dinv[64 + row] = 1.0f / vk;
            }
        }
        __syncthreads();

        // ---- prefetch next chunk's raw q/k (covered by GEMM + rank) ----
        if (ch + 1 < NCH) {
            const char* qs = (const char*)(q + sbase + (long long)(s0 + RCH) * Dc);
            const char* ks = (const char*)(k + sbase + (long long)(s0 + RCH) * Dc);
            #pragma unroll
            for (int j = 0; j < 8; j++) {
                int off = (tid + NTHREADS * j) * 16;
                cp_async16(rawq_s + off, qs + off);
                cp_async16(rawk_s + off, ks + off);
            }
            cp_commit();
        }

        // ---- GEMM: C[128][128] = Asm @ Msm, 8x8 thread tiles, f32x2 ----
        unsigned long long cacc[8][4];
        #pragma unroll
        for (int i = 0; i < 8; i++) {
            #pragma unroll
            for (int j = 0; j < 4; j++) cacc[i][j] = 0ULL;
        }
        {
            const float* arow = Asm + rg * 8 * Dc;
            #pragma unroll 2
            for (int k4 = 0; k4 < Dc / 4; k4++) {
                float4 a4[8];
                #pragma unroll
                for (int i = 0; i < 8; i++)
                    a4[i] = *(const float4*)(arow + i * Dc + k4 * 4);
                #pragma unroll
                for (int kk = 0; kk < 4; kk++) {
                    const ulonglong2* mp =
                        (const ulonglong2*)(Msm + (k4 * 4 + kk) * Dc + cols);
                    ulonglong2 b0 = mp[0];
                    ulonglong2 b1 = mp[1];
                    #pragma unroll
                    for (int i = 0; i < 8; i++) {
                        float av = (kk == 0) ? a4[i].x : (kk == 1) ? a4[i].y
                                 : (kk == 2) ? a4[i].z : a4[i].w;
                        unsigned long long a2 = dup2(av);
                        ffma2(cacc[i][0], a2, b0.x);
                        ffma2(cacc[i][1], a2, b0.y);
                        ffma2(cacc[i][2], a2, b1.x);
                        ffma2(cacc[i][3], a2, b1.y);
                    }
                }
            }
        }

        // ---- epilogue: rows<64 -> gated output; rows>=64 -> value-delta ----
        if (rg < 8) {       // q rows (warps 0-3, uniform)
            #pragma unroll
            for (int i = 0; i < 8; i++) {
                int row = rg * 8 + i;
                float inv = dinv[row];
                float c[8];
                unpack2(cacc[i][0], c[0], c[1]);
                unpack2(cacc[i][1], c[2], c[3]);
                unpack2(cacc[i][2], c[4], c[5]);
                unpack2(cacc[i][3], c[6], c[7]);
                const long long rowoff = sbase + (long long)(s0 + row) * Dc + cols;
                const float4* ap = (const float4*)(att + rowoff);
                float4 a0 = ap[0], a1 = ap[1];
                float4 o0, o1;
                o0.x = gg[0] * (c[0] * inv) + go[0] * a0.x;
                o0.y = gg[1] * (c[1] * inv) + go[1] * a0.y;
                o0.z = gg[2] * (c[2] * inv) + go[2] * a0.z;
                o0.w = gg[3] * (c[3] * inv) + go[3] * a0.w;
                o1.x = gg[4] * (c[4] * inv) + go[4] * a1.x;
                o1.y = gg[5] * (c[5] * inv) + go[5] * a1.y;
                o1.z = gg[6] * (c[6] * inv) + go[6] * a1.z;
                o1.w = gg[7] * (c[7] * inv) + go[7] * a1.w;
                float4* op = (float4*)(out + rowoff);
                op[0] = o0; op[1] = o1;
            }
        } else {            // k rows (warps 4-7): vd = v - retrieved -> VDsm
            #pragma unroll
            for (int i = 0; i < 8; i++) {
                int row = rg * 8 + i;          // 64..127
                int r   = row - 64;
                float inv = dinv[row];
                float c[8];
                unpack2(cacc[i][0], c[0], c[1]);
                unpack2(cacc[i][1], c[2], c[3]);
                unpack2(cacc[i][2], c[4], c[5]);
                unpack2(cacc[i][3], c[6], c[7]);
                const float4* vp =
                    (const float4*)(v + sbase + (long long)(s0 + r) * Dc + cols);
                float4 v0 = vp[0], v1 = vp[1];
                float4 w0, w1;
                w0.x = v0.x - c[0] * inv;  w0.y = v0.y - c[1] * inv;
                w0.z = v0.z - c[2] * inv;  w0.w = v0.w - c[3] * inv;
                w1.x = v1.x - c[4] * inv;  w1.y = v1.y - c[5] * inv;
                w1.z = v1.z - c[6] * inv;  w1.w = v1.w - c[7] * inv;
                float4* wp = (float4*)(VDsm + r * Dc + cols);
                wp[0] = w0; wp[1] = w1;
            }
        }
        __syncthreads();

        // ---- rank-64 update: racc[d][d'] += sk[r][d] * vd[r][d'] ----
        {
            const int drow = rg * 8;
            #pragma unroll 2
            for (int r = 0; r < RCH; r++) {
                const float* skr = Asm + (64 + r) * Dc + drow;
                float4 sA = *(const float4*)(skr);
                float4 sB = *(const float4*)(skr + 4);
                const ulonglong2* vp = (const ulonglong2*)(VDsm + r * Dc + cols);
                ulonglong2 b0 = vp[0];
                ulonglong2 b1 = vp[1];
                #pragma unroll
                for (int i = 0; i < 8; i++) {
                    float sv = (i == 0) ? sA.x : (i == 1) ? sA.y : (i == 2) ? sA.z
                             : (i == 3) ? sA.w : (i == 4) ? sB.x : (i == 5) ? sB.y
                             : (i == 6) ? sB.z : sB.w;
                    unsigned long long a2 = dup2(sv);
                    ffma2(racc[i][0], a2, b0.x);
                    ffma2(racc[i][1], a2, b0.y);
                    ffma2(racc[i][2], a2, b1.x);
                    ffma2(racc[i][3], a2, b1.y);
                }
            }
            if (tid < Dc) {
                float zs = 0.0f;
                #pragma unroll 8
                for (int r = 0; r < RCH; r++) zs += Asm[(64 + r) * Dc + tid];
                zacc += zs;
            }
        }
        __syncthreads();   // protect Asm/VDsm before next chunk
    }

    // ---- final: new_states = M + racc, new_z = z + zacc ----
    {
        float* ns = out + NS_OFF + (long long)bh * Dc * Dc;
        #pragma unroll
        for (int i = 0; i < 8; i++) {
            int drow = rg * 8 + i;
            float c[8];
            unpack2(racc[i][0], c[0], c[1]);
            unpack2(racc[i][1], c[2], c[3]);
            unpack2(racc[i][2], c[4], c[5]);
            unpack2(racc[i][3], c[6], c[7]);
            const float* mrow = Msm + drow * Dc + cols;
            float4 r0, r1;
            r0.x = c[0] + mrow[0];  r0.y = c[1] + mrow[1];
            r0.z = c[2] + mrow[2];  r0.w = c[3] + mrow[3];
            r1.x = c[4] + mrow[4];  r1.y = c[5] + mrow[5];
            r1.z = c[6] + mrow[6];  r1.w = c[7] + mrow[7];
            float4* np = (float4*)(ns + drow * Dc + cols);
            np[0] = r0; np[1] = r1;
        }
        if (tid < Dc) {
            out[NZ_OFF + (long long)bh * Dc + tid] = zsm[tid] + zacc;
        }
    }
}

extern "C" void kernel_launch(void* const* d_in, const int* in_sizes, int n_in,
                              void* d_out, int out_size) {
    (void)in_sizes; (void)n_in; (void)out_size;
    const float* q    = (const float*)d_in[0];
    const float* k    = (const float*)d_in[1];
    const float* v    = (const float*)d_in[2];
    const float* att  = (const float*)d_in[3];
    const float* bet  = (const float*)d_in[4];
    const float* mem0 = (const float*)d_in[5];
    const float* z0   = (const float*)d_in[6];
    float* out = (float*)d_out;

    const int smem_bytes = SM_TOT * (int)sizeof(float);   // 230912
    cudaFuncSetAttribute(pcm_kernel,
                         cudaFuncAttributeMaxDynamicSharedMemorySize, smem_bytes);
    pcm_kernel<<<Bc * Hc, NTHREADS, smem_bytes>>>(q, k, v, att, bet, mem0, z0, out);
}